// round 7
// baseline (speedup 1.0000x reference)
#include <cuda_runtime.h>

#define B_ 4
#define T_ 12
#define N_ 2000
#define K_ 10
#define F_ 64
#define H_ 8

// Scratch: y = x @ W^T (24.6 MB). Static __device__ (no cudaMalloc allowed).
__device__ float g_y[B_ * T_ * N_ * F_];

// ---- packed-fp32 helpers (FFMA2 only reachable via PTX) ---------------------
__device__ __forceinline__ unsigned long long pk2(float a, float b) {
    unsigned long long r;
    asm("mov.b64 %0, {%1, %2};" : "=l"(r)
        : "r"(__float_as_uint(a)), "r"(__float_as_uint(b)));
    return r;
}
__device__ __forceinline__ unsigned long long ffma2(unsigned long long a,
                                                    unsigned long long b,
                                                    unsigned long long c) {
    unsigned long long d;
    asm("fma.rn.f32x2 %0, %1, %2, %3;" : "=l"(d) : "l"(a), "l"(b), "l"(c));
    return d;
}
__device__ __forceinline__ float2 upk2(unsigned long long a) {
    unsigned int lo, hi;
    asm("mov.b64 {%0, %1}, %2;" : "=r"(lo), "=r"(hi) : "l"(a));
    return make_float2(__uint_as_float(lo), __uint_as_float(hi));
}

// ---------------------------------------------------------------------------
// Kernel 1: y[row,f] = sum_fp x[row,fp] * W[f,fp].
// 750 blocks x 256 threads; 128-row tile; thread = 8 rows x 4 f (FFMA2 pairs).
// ---------------------------------------------------------------------------
__global__ __launch_bounds__(256) void k_xw(const float* __restrict__ x,
                                            const float* __restrict__ W) {
    __shared__ float xs[128][64];                  // 32 KB
    __shared__ unsigned long long Wp[64][32];      // 16 KB: Wp[fp][f2]=(W[2f2][fp],W[2f2+1][fp])

    const int tid = threadIdx.x;

    // Build Wp: thread = (f2 = tid>>3, col-group cg = tid&7 covering fp cg*8..+7).
    {
        const int f2 = tid >> 3, cg = tid & 7;
        const float* ra = W + (2 * f2) * 64 + cg * 8;
        const float* rb = W + (2 * f2 + 1) * 64 + cg * 8;
        const float4 a0 = *(const float4*)ra;
        const float4 a1 = *(const float4*)(ra + 4);
        const float4 b0 = *(const float4*)rb;
        const float4 b1 = *(const float4*)(rb + 4);
        Wp[cg * 8 + 0][f2] = pk2(a0.x, b0.x);
        Wp[cg * 8 + 1][f2] = pk2(a0.y, b0.y);
        Wp[cg * 8 + 2][f2] = pk2(a0.z, b0.z);
        Wp[cg * 8 + 3][f2] = pk2(a0.w, b0.w);
        Wp[cg * 8 + 4][f2] = pk2(a1.x, b1.x);
        Wp[cg * 8 + 5][f2] = pk2(a1.y, b1.y);
        Wp[cg * 8 + 6][f2] = pk2(a1.z, b1.z);
        Wp[cg * 8 + 7][f2] = pk2(a1.w, b1.w);
    }

    const size_t rbase = (size_t)blockIdx.x * 128;
    const float4* xg = (const float4*)(x + rbase * F_);
    #pragma unroll
    for (int j = tid; j < 128 * 16; j += 256) {              // coalesced
        ((float4*)xs)[j] = xg[j];
    }
    __syncthreads();

    const int fx = tid & 15;       // f chunk: 4 floats = 2 ull
    const int rg = tid >> 4;       // rows rg*8 .. rg*8+7

    unsigned long long acc[8][2];
    #pragma unroll
    for (int r = 0; r < 8; ++r) { acc[r][0] = 0ull; acc[r][1] = 0ull; }

    #pragma unroll 4
    for (int fps = 0; fps < 16; ++fps) {
        const int fp = fps * 4;
        unsigned long long w0[4], w1[4];
        #pragma unroll
        for (int i = 0; i < 4; ++i) {
            const ulonglong2 wv = *(const ulonglong2*)&Wp[fp + i][fx * 2];
            w0[i] = wv.x; w1[i] = wv.y;            // conflict-free
        }
        #pragma unroll
        for (int r = 0; r < 8; ++r) {
            const float4 xv = *(const float4*)&xs[rg * 8 + r][fp];   // broadcast
            unsigned long long xd;
            xd = pk2(xv.x, xv.x);
            acc[r][0] = ffma2(xd, w0[0], acc[r][0]); acc[r][1] = ffma2(xd, w1[0], acc[r][1]);
            xd = pk2(xv.y, xv.y);
            acc[r][0] = ffma2(xd, w0[1], acc[r][0]); acc[r][1] = ffma2(xd, w1[1], acc[r][1]);
            xd = pk2(xv.z, xv.z);
            acc[r][0] = ffma2(xd, w0[2], acc[r][0]); acc[r][1] = ffma2(xd, w1[2], acc[r][1]);
            xd = pk2(xv.w, xv.w);
            acc[r][0] = ffma2(xd, w0[3], acc[r][0]); acc[r][1] = ffma2(xd, w1[3], acc[r][1]);
        }
    }

    float* yp = g_y + rbase * F_;
    #pragma unroll
    for (int r = 0; r < 8; ++r) {
        const float2 lo = upk2(acc[r][0]);
        const float2 hi = upk2(acc[r][1]);
        *(float4*)&yp[(rg * 8 + r) * F_ + fx * 4] = make_float4(lo.x, lo.y, hi.x, hi.y);
    }
}

// ---------------------------------------------------------------------------
// Kernel 2: gather + heads + blend + relu.
// Thread = (node nl 0..3, head h 0..7, f-chunk fo 0..7) — ONE head per thread:
// the duplicated weight table is 10 ull (20 regs), half of R5. Each thread
// covers float4 chunks fo and fo+8 (128 B apart) so every LDG.128 spans a full
// 128B line -> L1 wavefronts identical to R5. Indices in smem as LDS.32
// broadcasts (1 phase each). Output via __stcs (write-once stream, keeps y in
// L2). ~55 regs -> 4 CTAs/SM. prev carries the UNBLENDED agg[t-1]; t=0 peeled.
// ---------------------------------------------------------------------------
__global__ __launch_bounds__(256, 4) void k_gather(
    const float* __restrict__ dist,
    const float* __restrict__ bias,
    const int* __restrict__ nidx,          // int32 (JAX x64 disabled)
    float* __restrict__ out) {

    __shared__ int sidx[4][K_];            // pre-scaled float4 indices

    const int tid = threadIdx.x;
    const int fo  = tid & 7;               // f4-chunks fo and fo+8
    const int h   = (tid >> 3) & 7;        // head
    const int nl  = tid >> 6;              // node within block
    const int bb  = blockIdx.y;
    const int n   = blockIdx.x * 4 + nl;

    if (tid < 4 * K_) {
        sidx[tid / K_][tid % K_] =
            __ldg(&nidx[(blockIdx.x * 4 + tid / K_) * K_ + tid % K_]) * (F_ / 4);
    }

    // Duplicated weight pairs for this thread's single head (10 ull).
    unsigned long long wd[K_];
    const float hf = (float)(h + 1);
    #pragma unroll
    for (int k = 0; k < K_; ++k) {
        const float d = __ldg(&dist[n * K_ + k]);
        const float w = __expf(-d * d * hf * (1.0f / (H_ * 36.0f)));
        wd[k] = pk2(w, w);
    }
    __syncthreads();

    // Bias for both chunks (floats fo*4.. and fo*4+32..).
    const float4 bva = *(const float4*)(bias + fo * 4);
    const float4 bvb = *(const float4*)(bias + fo * 4 + 32);
    const unsigned long long ba01 = pk2(bva.x, bva.y);
    const unsigned long long ba23 = pk2(bva.z, bva.w);
    const unsigned long long bb01 = pk2(bvb.x, bvb.y);
    const unsigned long long bb23 = pk2(bvb.z, bvb.w);

    const int* sx = sidx[nl];
    const float4* yb = (const float4*)g_y + (size_t)(bb * T_) * N_ * (F_ / 4) + fo;
    float* ob = out + ((size_t)(bb * T_ * N_) + n) * (H_ * F_) + h * F_ + fo * 4;

    unsigned long long prev[4];
    unsigned long long acc[4];

    const unsigned long long c0d = pk2(0.8f, 0.8f);
    const unsigned long long c1d = pk2(0.2f, 0.2f);

    #pragma unroll 1
    for (int t = 0; t < T_; ++t) {
        acc[0] = 0ull; acc[1] = 0ull; acc[2] = 0ull; acc[3] = 0ull;
        #pragma unroll
        for (int k = 0; k < K_; ++k) {               // 20 independent LDG.128
            const float4* row = yb + sx[k];          // LDS.32 broadcast + IADD
            const float4 ya = __ldg(row);            // chunk A: full 128B line/warp
            const float4 yc = __ldg(row + 8);        // chunk B: +128B, imm offset
            acc[0] = ffma2(pk2(ya.x, ya.y), wd[k], acc[0]);
            acc[1] = ffma2(pk2(ya.z, ya.w), wd[k], acc[1]);
            acc[2] = ffma2(pk2(yc.x, yc.y), wd[k], acc[2]);
            acc[3] = ffma2(pk2(yc.z, yc.w), wd[k], acc[3]);
        }

        unsigned long long r0, r1, r2, r3;
        if (t == 0) {
            r0 = ffma2(acc[0], pk2(1.f, 1.f), ba01);
            r1 = ffma2(acc[1], pk2(1.f, 1.f), ba23);
            r2 = ffma2(acc[2], pk2(1.f, 1.f), bb01);
            r3 = ffma2(acc[3], pk2(1.f, 1.f), bb23);
        } else {
            r0 = ffma2(acc[0], c0d, ffma2(prev[0], c1d, ba01));
            r1 = ffma2(acc[1], c0d, ffma2(prev[1], c1d, ba23));
            r2 = ffma2(acc[2], c0d, ffma2(prev[2], c1d, bb01));
            r3 = ffma2(acc[3], c0d, ffma2(prev[3], c1d, bb23));
        }
        prev[0] = acc[0]; prev[1] = acc[1];          // UNBLENDED carry
        prev[2] = acc[2]; prev[3] = acc[3];

        const float2 v0 = upk2(r0), v1 = upk2(r1), v2 = upk2(r2), v3 = upk2(r3);
        __stcs((float4*)ob,
               make_float4(fmaxf(v0.x, 0.f), fmaxf(v0.y, 0.f),
                           fmaxf(v1.x, 0.f), fmaxf(v1.y, 0.f)));
        __stcs((float4*)(ob + 32),
               make_float4(fmaxf(v2.x, 0.f), fmaxf(v2.y, 0.f),
                           fmaxf(v3.x, 0.f), fmaxf(v3.y, 0.f)));

        yb += N_ * (F_ / 4);                         // next t
        ob += (size_t)N_ * (H_ * F_);
    }
}

// ---------------------------------------------------------------------------
// Inputs: x f32[4,12,2000,64], neighbor_dist f32[2000,10], W f32[64,64],
// b f32[64], neighbor_idx i32[2000,10]. Output f32[4,12,2000,8,64].
// ---------------------------------------------------------------------------
extern "C" void kernel_launch(void* const* d_in, const int* in_sizes, int n_in,
                              void* d_out, int out_size) {
    const float* x    = (const float*)d_in[0];
    const float* dist = (const float*)d_in[1];
    const float* W    = (const float*)d_in[2];
    const float* bias = (const float*)d_in[3];
    const int*   nidx = (const int*)d_in[4];
    float*       out  = (float*)d_out;

    k_xw<<<(B_ * T_ * N_) / 128, 256>>>(x, W);

    dim3 g2(N_ / 4, B_);
    k_gather<<<g2, 256>>>(dist, bias, nidx, out);
}

// round 8
// speedup vs baseline: 1.2834x; 1.2834x over previous
#include <cuda_runtime.h>

#define B_ 4
#define T_ 12
#define N_ 2000
#define K_ 10
#define F_ 64
#define H_ 8

// Scratch: y = x @ W^T (24.6 MB). Static __device__ (no cudaMalloc allowed).
__device__ float g_y[B_ * T_ * N_ * F_];

// ---- packed-fp32 helpers (FFMA2 only reachable via PTX) ---------------------
__device__ __forceinline__ unsigned long long pk2(float a, float b) {
    unsigned long long r;
    asm("mov.b64 %0, {%1, %2};" : "=l"(r)
        : "r"(__float_as_uint(a)), "r"(__float_as_uint(b)));
    return r;
}
__device__ __forceinline__ unsigned long long ffma2(unsigned long long a,
                                                    unsigned long long b,
                                                    unsigned long long c) {
    unsigned long long d;
    asm("fma.rn.f32x2 %0, %1, %2, %3;" : "=l"(d) : "l"(a), "l"(b), "l"(c));
    return d;
}
__device__ __forceinline__ float2 upk2(unsigned long long a) {
    unsigned int lo, hi;
    asm("mov.b64 {%0, %1}, %2;" : "=r"(lo), "=r"(hi) : "l"(a));
    return make_float2(__uint_as_float(lo), __uint_as_float(hi));
}

// ---------------------------------------------------------------------------
// Kernel 1: y[row,f] = sum_fp x[row,fp] * W[f,fp].
// 750 blocks x 256 threads; 128-row tile; thread = 8 rows x 4 f (FFMA2 pairs).
// ---------------------------------------------------------------------------
__global__ __launch_bounds__(256) void k_xw(const float* __restrict__ x,
                                            const float* __restrict__ W) {
    __shared__ float xs[128][64];                  // 32 KB
    __shared__ unsigned long long Wp[64][32];      // 16 KB: Wp[fp][f2]=(W[2f2][fp],W[2f2+1][fp])

    const int tid = threadIdx.x;

    // Build Wp: thread = (f2 = tid>>3, col-group cg = tid&7 covering fp cg*8..+7).
    {
        const int f2 = tid >> 3, cg = tid & 7;
        const float* ra = W + (2 * f2) * 64 + cg * 8;
        const float* rb = W + (2 * f2 + 1) * 64 + cg * 8;
        const float4 a0 = *(const float4*)ra;
        const float4 a1 = *(const float4*)(ra + 4);
        const float4 b0 = *(const float4*)rb;
        const float4 b1 = *(const float4*)(rb + 4);
        Wp[cg * 8 + 0][f2] = pk2(a0.x, b0.x);
        Wp[cg * 8 + 1][f2] = pk2(a0.y, b0.y);
        Wp[cg * 8 + 2][f2] = pk2(a0.z, b0.z);
        Wp[cg * 8 + 3][f2] = pk2(a0.w, b0.w);
        Wp[cg * 8 + 4][f2] = pk2(a1.x, b1.x);
        Wp[cg * 8 + 5][f2] = pk2(a1.y, b1.y);
        Wp[cg * 8 + 6][f2] = pk2(a1.z, b1.z);
        Wp[cg * 8 + 7][f2] = pk2(a1.w, b1.w);
    }

    const size_t rbase = (size_t)blockIdx.x * 128;
    const float4* xg = (const float4*)(x + rbase * F_);
    #pragma unroll
    for (int j = tid; j < 128 * 16; j += 256) {              // coalesced
        ((float4*)xs)[j] = xg[j];
    }
    __syncthreads();

    const int fx = tid & 15;       // f chunk: 4 floats = 2 ull
    const int rg = tid >> 4;       // rows rg*8 .. rg*8+7

    unsigned long long acc[8][2];
    #pragma unroll
    for (int r = 0; r < 8; ++r) { acc[r][0] = 0ull; acc[r][1] = 0ull; }

    #pragma unroll 4
    for (int fps = 0; fps < 16; ++fps) {
        const int fp = fps * 4;
        unsigned long long w0[4], w1[4];
        #pragma unroll
        for (int i = 0; i < 4; ++i) {
            const ulonglong2 wv = *(const ulonglong2*)&Wp[fp + i][fx * 2];
            w0[i] = wv.x; w1[i] = wv.y;            // conflict-free
        }
        #pragma unroll
        for (int r = 0; r < 8; ++r) {
            const float4 xv = *(const float4*)&xs[rg * 8 + r][fp];   // broadcast
            unsigned long long xd;
            xd = pk2(xv.x, xv.x);
            acc[r][0] = ffma2(xd, w0[0], acc[r][0]); acc[r][1] = ffma2(xd, w1[0], acc[r][1]);
            xd = pk2(xv.y, xv.y);
            acc[r][0] = ffma2(xd, w0[1], acc[r][0]); acc[r][1] = ffma2(xd, w1[1], acc[r][1]);
            xd = pk2(xv.z, xv.z);
            acc[r][0] = ffma2(xd, w0[2], acc[r][0]); acc[r][1] = ffma2(xd, w1[2], acc[r][1]);
            xd = pk2(xv.w, xv.w);
            acc[r][0] = ffma2(xd, w0[3], acc[r][0]); acc[r][1] = ffma2(xd, w1[3], acc[r][1]);
        }
    }

    float* yp = g_y + rbase * F_;
    #pragma unroll
    for (int r = 0; r < 8; ++r) {
        const float2 lo = upk2(acc[r][0]);
        const float2 hi = upk2(acc[r][1]);
        *(float4*)&yp[(rg * 8 + r) * F_ + fx * 4] = make_float4(lo.x, lo.y, hi.x, hi.y);
    }
}

// ---------------------------------------------------------------------------
// Kernel 2: gather + heads + blend + relu.
// WARP = one node; LANE = one f-pair (F=64 -> 32 float2 lanes).
// Every gather is ONE warp-wide LDG.64 with 32 DISTINCT lanes = 256B fully
// dense (2 wavefronts, zero duplication — the R5/R7 gathers wasted 50-75% of
// their wavefronts on replicated lane addresses). Each lane accumulates all 8
// heads (8 acc + 8 prev ull); duplicated weights live in smem and are read as
// LDS.128 TRUE broadcasts (all lanes same address -> 1 wavefront). Stores are
// 8 STG.64, lanes contiguous (2 wf each, minimal), streaming (__stcs) so the
// out-stream doesn't evict L2-resident y. prev carries UNBLENDED agg[t-1].
// ---------------------------------------------------------------------------
__global__ __launch_bounds__(256, 4) void k_gather(
    const float* __restrict__ dist,
    const float* __restrict__ bias,
    const int* __restrict__ nidx,          // int32 (JAX x64 disabled)
    float* __restrict__ out) {

    __shared__ ulonglong2 swt[8][K_][4];   // [nl][k][j]=(dup w_{2j+1..}, heads 2j,2j+1)

    const int tid  = threadIdx.x;
    const int lane = tid & 31;             // f-pair
    const int wpid = tid >> 5;             // node within block (8 warps)
    const int bb   = blockIdx.y;
    const int n0   = blockIdx.x * 8;
    const int n    = n0 + wpid;

    // Cooperative weight-table build: 640 dup-pairs, one per (nl,k,h).
    #pragma unroll
    for (int j = tid; j < 8 * K_ * H_; j += 256) {
        const int e_nl = j / (K_ * H_);
        const int r    = j % (K_ * H_);
        const int e_k  = r >> 3;
        const int e_h  = r & 7;
        const float d = __ldg(&dist[(n0 + e_nl) * K_ + e_k]);
        const float w = __expf(-d * d * (float)(e_h + 1) * (1.0f / (H_ * 36.0f)));
        ((unsigned long long*)swt)[j] = pk2(w, w);
    }

    // Gather indices in registers (broadcast loads), pre-scaled to float2 units.
    int sx[K_];
    #pragma unroll
    for (int k = 0; k < K_; ++k)
        sx[k] = __ldg(&nidx[n * K_ + k]) * (F_ / 2);

    __syncthreads();

    const unsigned long long bdup =
        __ldg((const unsigned long long*)bias + lane);   // (b[2l], b[2l+1]) natural pair

    const unsigned long long* yb =
        (const unsigned long long*)g_y + (size_t)(bb * T_) * N_ * (F_ / 2) + lane;
    float2* ob = (float2*)out + ((size_t)(bb * T_ * N_) + n) * (H_ * F_ / 2) + lane;

    const ulonglong2* wrow = swt[wpid][0];   // index k*4 + j (uniform per warp)

    unsigned long long prev[H_];
    unsigned long long acc[H_];
    const unsigned long long c0d = pk2(0.8f, 0.8f);
    const unsigned long long c1d = pk2(0.2f, 0.2f);
    const unsigned long long one = pk2(1.0f, 1.0f);

    #pragma unroll 1
    for (int t = 0; t < T_; ++t) {
        #pragma unroll
        for (int h = 0; h < H_; ++h) acc[h] = 0ull;

        #pragma unroll
        for (int k = 0; k < K_; ++k) {
            const unsigned long long yv = __ldg(yb + sx[k]);   // dense LDG.64
            const ulonglong2 w01 = wrow[k * 4 + 0];            // LDS.128 broadcast
            const ulonglong2 w23 = wrow[k * 4 + 1];
            const ulonglong2 w45 = wrow[k * 4 + 2];
            const ulonglong2 w67 = wrow[k * 4 + 3];
            acc[0] = ffma2(yv, w01.x, acc[0]);
            acc[1] = ffma2(yv, w01.y, acc[1]);
            acc[2] = ffma2(yv, w23.x, acc[2]);
            acc[3] = ffma2(yv, w23.y, acc[3]);
            acc[4] = ffma2(yv, w45.x, acc[4]);
            acc[5] = ffma2(yv, w45.y, acc[5]);
            acc[6] = ffma2(yv, w67.x, acc[6]);
            acc[7] = ffma2(yv, w67.y, acc[7]);
        }

        if (t == 0) {
            #pragma unroll
            for (int h = 0; h < H_; ++h) {
                const float2 v = upk2(ffma2(acc[h], one, bdup));
                __stcs(&ob[h * (F_ / 2)],
                       make_float2(fmaxf(v.x, 0.f), fmaxf(v.y, 0.f)));
                prev[h] = acc[h];
            }
        } else {
            #pragma unroll
            for (int h = 0; h < H_; ++h) {
                const float2 v =
                    upk2(ffma2(acc[h], c0d, ffma2(prev[h], c1d, bdup)));
                __stcs(&ob[h * (F_ / 2)],
                       make_float2(fmaxf(v.x, 0.f), fmaxf(v.y, 0.f)));
                prev[h] = acc[h];                  // UNBLENDED carry
            }
        }

        yb += N_ * (F_ / 2);
        ob += (size_t)N_ * (H_ * F_ / 2);
    }
}

// ---------------------------------------------------------------------------
// Inputs: x f32[4,12,2000,64], neighbor_dist f32[2000,10], W f32[64,64],
// b f32[64], neighbor_idx i32[2000,10]. Output f32[4,12,2000,8,64].
// ---------------------------------------------------------------------------
extern "C" void kernel_launch(void* const* d_in, const int* in_sizes, int n_in,
                              void* d_out, int out_size) {
    const float* x    = (const float*)d_in[0];
    const float* dist = (const float*)d_in[1];
    const float* W    = (const float*)d_in[2];
    const float* bias = (const float*)d_in[3];
    const int*   nidx = (const int*)d_in[4];
    float*       out  = (float*)d_out;

    k_xw<<<(B_ * T_ * N_) / 128, 256>>>(x, W);

    dim3 g2(N_ / 8, B_);
    k_gather<<<g2, 256>>>(dist, bias, nidx, out);
}

// round 9
// speedup vs baseline: 1.5670x; 1.2209x over previous
#include <cuda_runtime.h>

#define B_ 4
#define T_ 12
#define N_ 2000
#define K_ 10
#define F_ 64
#define H_ 8

// Scratch: y = x @ W^T (24.6 MB). Static __device__ (no cudaMalloc allowed).
__device__ float g_y[B_ * T_ * N_ * F_];

// ---- packed-fp32 helpers (f32x2 ops only reachable via PTX) -----------------
__device__ __forceinline__ unsigned long long pk2(float a, float b) {
    unsigned long long r;
    asm("mov.b64 %0, {%1, %2};" : "=l"(r)
        : "r"(__float_as_uint(a)), "r"(__float_as_uint(b)));
    return r;
}
__device__ __forceinline__ unsigned long long ffma2(unsigned long long a,
                                                    unsigned long long b,
                                                    unsigned long long c) {
    unsigned long long d;
    asm("fma.rn.f32x2 %0, %1, %2, %3;" : "=l"(d) : "l"(a), "l"(b), "l"(c));
    return d;
}
__device__ __forceinline__ unsigned long long mul2(unsigned long long a,
                                                   unsigned long long b) {
    unsigned long long d;
    asm("mul.rn.f32x2 %0, %1, %2;" : "=l"(d) : "l"(a), "l"(b));
    return d;
}
__device__ __forceinline__ unsigned long long add2(unsigned long long a,
                                                   unsigned long long b) {
    unsigned long long d;
    asm("add.rn.f32x2 %0, %1, %2;" : "=l"(d) : "l"(a), "l"(b));
    return d;
}
__device__ __forceinline__ float2 upk2(unsigned long long a) {
    unsigned int lo, hi;
    asm("mov.b64 {%0, %1}, %2;" : "=r"(lo), "=r"(hi) : "l"(a));
    return make_float2(__uint_as_float(lo), __uint_as_float(hi));
}

// ---------------------------------------------------------------------------
// Kernel 1: y[row,f] = sum_fp x[row,fp] * W[f,fp].
// 750 blocks x 256 threads; 128-row tile; thread = 8 rows x 4 f (FFMA2 pairs).
// ---------------------------------------------------------------------------
__global__ __launch_bounds__(256) void k_xw(const float* __restrict__ x,
                                            const float* __restrict__ W) {
    __shared__ float xs[128][64];                  // 32 KB
    __shared__ unsigned long long Wp[64][32];      // 16 KB: Wp[fp][f2]=(W[2f2][fp],W[2f2+1][fp])

    const int tid = threadIdx.x;

    // Build Wp: thread = (f2 = tid>>3, col-group cg = tid&7 covering fp cg*8..+7).
    {
        const int f2 = tid >> 3, cg = tid & 7;
        const float* ra = W + (2 * f2) * 64 + cg * 8;
        const float* rb = W + (2 * f2 + 1) * 64 + cg * 8;
        const float4 a0 = *(const float4*)ra;
        const float4 a1 = *(const float4*)(ra + 4);
        const float4 b0 = *(const float4*)rb;
        const float4 b1 = *(const float4*)(rb + 4);
        Wp[cg * 8 + 0][f2] = pk2(a0.x, b0.x);
        Wp[cg * 8 + 1][f2] = pk2(a0.y, b0.y);
        Wp[cg * 8 + 2][f2] = pk2(a0.z, b0.z);
        Wp[cg * 8 + 3][f2] = pk2(a0.w, b0.w);
        Wp[cg * 8 + 4][f2] = pk2(a1.x, b1.x);
        Wp[cg * 8 + 5][f2] = pk2(a1.y, b1.y);
        Wp[cg * 8 + 6][f2] = pk2(a1.z, b1.z);
        Wp[cg * 8 + 7][f2] = pk2(a1.w, b1.w);
    }

    const size_t rbase = (size_t)blockIdx.x * 128;
    const float4* xg = (const float4*)(x + rbase * F_);
    #pragma unroll
    for (int j = tid; j < 128 * 16; j += 256) {              // coalesced
        ((float4*)xs)[j] = xg[j];
    }
    __syncthreads();

    const int fx = tid & 15;       // f chunk: 4 floats = 2 ull
    const int rg = tid >> 4;       // rows rg*8 .. rg*8+7

    unsigned long long acc[8][2];
    #pragma unroll
    for (int r = 0; r < 8; ++r) { acc[r][0] = 0ull; acc[r][1] = 0ull; }

    #pragma unroll 4
    for (int fps = 0; fps < 16; ++fps) {
        const int fp = fps * 4;
        unsigned long long w0[4], w1[4];
        #pragma unroll
        for (int i = 0; i < 4; ++i) {
            const ulonglong2 wv = *(const ulonglong2*)&Wp[fp + i][fx * 2];
            w0[i] = wv.x; w1[i] = wv.y;            // conflict-free
        }
        #pragma unroll
        for (int r = 0; r < 8; ++r) {
            const float4 xv = *(const float4*)&xs[rg * 8 + r][fp];   // broadcast
            unsigned long long xd;
            xd = pk2(xv.x, xv.x);
            acc[r][0] = ffma2(xd, w0[0], acc[r][0]); acc[r][1] = ffma2(xd, w1[0], acc[r][1]);
            xd = pk2(xv.y, xv.y);
            acc[r][0] = ffma2(xd, w0[1], acc[r][0]); acc[r][1] = ffma2(xd, w1[1], acc[r][1]);
            xd = pk2(xv.z, xv.z);
            acc[r][0] = ffma2(xd, w0[2], acc[r][0]); acc[r][1] = ffma2(xd, w1[2], acc[r][1]);
            xd = pk2(xv.w, xv.w);
            acc[r][0] = ffma2(xd, w0[3], acc[r][0]); acc[r][1] = ffma2(xd, w1[3], acc[r][1]);
        }
    }

    float* yp = g_y + rbase * F_;
    #pragma unroll
    for (int r = 0; r < 8; ++r) {
        const float2 lo = upk2(acc[r][0]);
        const float2 hi = upk2(acc[r][1]);
        *(float4*)&yp[(rg * 8 + r) * F_ + fx * 4] = make_float4(lo.x, lo.y, hi.x, hi.y);
    }
}

// ---------------------------------------------------------------------------
// Kernel 2: gather + heads + blend + relu.
// WARP = one node; LANE = one f-pair (dense warp-wide LDG.64 gathers, 2 wf,
// zero waste). KEY: w[n,k,h] = r_k^(h+1) with r_k = exp(-d^2/288) — a
// geometric chain per k. Only 10 dup-pairs rd[k] live in registers; the 8
// head-products are generated in-flight (cur = cur*rd; acc[h] += cur), which
// DELETES the entire in-loop smem weight table (R8's 80 wf/node-t of LDS).
// No smem, no __syncthreads anywhere. prev carries UNBLENDED agg[t-1];
// streaming stores keep the 24.6MB y L2-resident under the 197MB out-stream.
// ---------------------------------------------------------------------------
__global__ __launch_bounds__(256, 3) void k_gather(
    const float* __restrict__ dist,
    const float* __restrict__ bias,
    const int* __restrict__ nidx,          // int32 (JAX x64 disabled)
    float* __restrict__ out) {

    const int tid  = threadIdx.x;
    const int lane = tid & 31;             // f-pair
    const int wpid = tid >> 5;             // node within block (8 warps)
    const int bb   = blockIdx.y;
    const int n    = blockIdx.x * 8 + wpid;

    // Per-k ratio rd[k] = dup(exp(-d^2/288)) and gather index (registers).
    unsigned long long rd[K_];
    int sx[K_];
    #pragma unroll
    for (int k = 0; k < K_; ++k) {
        const float d = __ldg(&dist[n * K_ + k]);           // warp-broadcast
        const float r = __expf(-d * d * (1.0f / (H_ * 36.0f)));
        rd[k] = pk2(r, r);
        sx[k] = __ldg(&nidx[n * K_ + k]) * (F_ / 2);
    }

    const unsigned long long bdup =
        __ldg((const unsigned long long*)bias + lane);      // (b[2l], b[2l+1])

    const unsigned long long* yb =
        (const unsigned long long*)g_y + (size_t)(bb * T_) * N_ * (F_ / 2) + lane;
    float2* ob = (float2*)out + ((size_t)(bb * T_ * N_) + n) * (H_ * F_ / 2) + lane;

    unsigned long long prev[H_];
    unsigned long long acc[H_];
    const unsigned long long c0d = pk2(0.8f, 0.8f);
    const unsigned long long c1d = pk2(0.2f, 0.2f);
    const unsigned long long one = pk2(1.0f, 1.0f);

    #pragma unroll 1
    for (int t = 0; t < T_; ++t) {
        #pragma unroll
        for (int h = 0; h < H_; ++h) acc[h] = 0ull;

        #pragma unroll
        for (int k = 0; k < K_; ++k) {
            unsigned long long cur = __ldg(yb + sx[k]);     // dense LDG.64
            #pragma unroll
            for (int h = 0; h < H_; ++h) {                  // geometric chain
                cur = mul2(cur, rd[k]);                     // y * r^(h+1)
                acc[h] = add2(acc[h], cur);
            }
        }

        if (t == 0) {
            #pragma unroll
            for (int h = 0; h < H_; ++h) {
                const float2 v = upk2(ffma2(acc[h], one, bdup));
                __stcs(&ob[h * (F_ / 2)],
                       make_float2(fmaxf(v.x, 0.f), fmaxf(v.y, 0.f)));
                prev[h] = acc[h];
            }
        } else {
            #pragma unroll
            for (int h = 0; h < H_; ++h) {
                const float2 v =
                    upk2(ffma2(acc[h], c0d, ffma2(prev[h], c1d, bdup)));
                __stcs(&ob[h * (F_ / 2)],
                       make_float2(fmaxf(v.x, 0.f), fmaxf(v.y, 0.f)));
                prev[h] = acc[h];                  // UNBLENDED carry
            }
        }

        yb += N_ * (F_ / 2);
        ob += (size_t)N_ * (H_ * F_ / 2);
    }
}

// ---------------------------------------------------------------------------
// Inputs: x f32[4,12,2000,64], neighbor_dist f32[2000,10], W f32[64,64],
// b f32[64], neighbor_idx i32[2000,10]. Output f32[4,12,2000,8,64].
// ---------------------------------------------------------------------------
extern "C" void kernel_launch(void* const* d_in, const int* in_sizes, int n_in,
                              void* d_out, int out_size) {
    const float* x    = (const float*)d_in[0];
    const float* dist = (const float*)d_in[1];
    const float* W    = (const float*)d_in[2];
    const float* bias = (const float*)d_in[3];
    const int*   nidx = (const int*)d_in[4];
    float*       out  = (float*)d_out;

    k_xw<<<(B_ * T_ * N_) / 128, 256>>>(x, W);

    dim3 g2(N_ / 8, B_);
    k_gather<<<g2, 256>>>(dist, bias, nidx, out);
}

// round 10
// speedup vs baseline: 1.6568x; 1.0574x over previous
#include <cuda_runtime.h>

#define B_ 4
#define T_ 12
#define N_ 2000
#define K_ 10
#define F_ 64
#define H_ 8

// Scratch: y = x @ W^T (24.6 MB). Static __device__ (no cudaMalloc allowed).
__device__ float g_y[B_ * T_ * N_ * F_];

// ---- packed-fp32 helpers (f32x2 ops only reachable via PTX) -----------------
__device__ __forceinline__ unsigned long long pk2(float a, float b) {
    unsigned long long r;
    asm("mov.b64 %0, {%1, %2};" : "=l"(r)
        : "r"(__float_as_uint(a)), "r"(__float_as_uint(b)));
    return r;
}
__device__ __forceinline__ unsigned long long ffma2(unsigned long long a,
                                                    unsigned long long b,
                                                    unsigned long long c) {
    unsigned long long d;
    asm("fma.rn.f32x2 %0, %1, %2, %3;" : "=l"(d) : "l"(a), "l"(b), "l"(c));
    return d;
}
__device__ __forceinline__ unsigned long long mul2(unsigned long long a,
                                                   unsigned long long b) {
    unsigned long long d;
    asm("mul.rn.f32x2 %0, %1, %2;" : "=l"(d) : "l"(a), "l"(b));
    return d;
}
__device__ __forceinline__ unsigned long long add2(unsigned long long a,
                                                   unsigned long long b) {
    unsigned long long d;
    asm("add.rn.f32x2 %0, %1, %2;" : "=l"(d) : "l"(a), "l"(b));
    return d;
}
__device__ __forceinline__ float2 upk2(unsigned long long a) {
    unsigned int lo, hi;
    asm("mov.b64 {%0, %1}, %2;" : "=r"(lo), "=r"(hi) : "l"(a));
    return make_float2(__uint_as_float(lo), __uint_as_float(hi));
}

// ---------------------------------------------------------------------------
// Kernel 1: y[row,f] = sum_fp x[row,fp] * W[f,fp].
// 750 blocks x 256 threads; 128-row tile; thread = 8 rows x 4 f (FFMA2 pairs).
// ---------------------------------------------------------------------------
__global__ __launch_bounds__(256) void k_xw(const float* __restrict__ x,
                                            const float* __restrict__ W) {
    __shared__ float xs[128][64];                  // 32 KB
    __shared__ unsigned long long Wp[64][32];      // 16 KB: Wp[fp][f2]=(W[2f2][fp],W[2f2+1][fp])

    const int tid = threadIdx.x;

    // Build Wp: thread = (f2 = tid>>3, col-group cg = tid&7 covering fp cg*8..+7).
    {
        const int f2 = tid >> 3, cg = tid & 7;
        const float* ra = W + (2 * f2) * 64 + cg * 8;
        const float* rb = W + (2 * f2 + 1) * 64 + cg * 8;
        const float4 a0 = *(const float4*)ra;
        const float4 a1 = *(const float4*)(ra + 4);
        const float4 b0 = *(const float4*)rb;
        const float4 b1 = *(const float4*)(rb + 4);
        Wp[cg * 8 + 0][f2] = pk2(a0.x, b0.x);
        Wp[cg * 8 + 1][f2] = pk2(a0.y, b0.y);
        Wp[cg * 8 + 2][f2] = pk2(a0.z, b0.z);
        Wp[cg * 8 + 3][f2] = pk2(a0.w, b0.w);
        Wp[cg * 8 + 4][f2] = pk2(a1.x, b1.x);
        Wp[cg * 8 + 5][f2] = pk2(a1.y, b1.y);
        Wp[cg * 8 + 6][f2] = pk2(a1.z, b1.z);
        Wp[cg * 8 + 7][f2] = pk2(a1.w, b1.w);
    }

    const size_t rbase = (size_t)blockIdx.x * 128;
    const float4* xg = (const float4*)(x + rbase * F_);
    #pragma unroll
    for (int j = tid; j < 128 * 16; j += 256) {              // coalesced
        ((float4*)xs)[j] = xg[j];
    }
    __syncthreads();

    const int fx = tid & 15;       // f chunk: 4 floats = 2 ull
    const int rg = tid >> 4;       // rows rg*8 .. rg*8+7

    unsigned long long acc[8][2];
    #pragma unroll
    for (int r = 0; r < 8; ++r) { acc[r][0] = 0ull; acc[r][1] = 0ull; }

    #pragma unroll 4
    for (int fps = 0; fps < 16; ++fps) {
        const int fp = fps * 4;
        unsigned long long w0[4], w1[4];
        #pragma unroll
        for (int i = 0; i < 4; ++i) {
            const ulonglong2 wv = *(const ulonglong2*)&Wp[fp + i][fx * 2];
            w0[i] = wv.x; w1[i] = wv.y;            // conflict-free
        }
        #pragma unroll
        for (int r = 0; r < 8; ++r) {
            const float4 xv = *(const float4*)&xs[rg * 8 + r][fp];   // broadcast
            unsigned long long xd;
            xd = pk2(xv.x, xv.x);
            acc[r][0] = ffma2(xd, w0[0], acc[r][0]); acc[r][1] = ffma2(xd, w1[0], acc[r][1]);
            xd = pk2(xv.y, xv.y);
            acc[r][0] = ffma2(xd, w0[1], acc[r][0]); acc[r][1] = ffma2(xd, w1[1], acc[r][1]);
            xd = pk2(xv.z, xv.z);
            acc[r][0] = ffma2(xd, w0[2], acc[r][0]); acc[r][1] = ffma2(xd, w1[2], acc[r][1]);
            xd = pk2(xv.w, xv.w);
            acc[r][0] = ffma2(xd, w0[3], acc[r][0]); acc[r][1] = ffma2(xd, w1[3], acc[r][1]);
        }
    }

    float* yp = g_y + rbase * F_;
    #pragma unroll
    for (int r = 0; r < 8; ++r) {
        const float2 lo = upk2(acc[r][0]);
        const float2 hi = upk2(acc[r][1]);
        *(float4*)&yp[(rg * 8 + r) * F_ + fx * 4] = make_float4(lo.x, lo.y, hi.x, hi.y);
    }
}

// ---------------------------------------------------------------------------
// Kernel 2: gather + heads + blend + relu.
// WARP = one node; LANE = one f-pair (dense warp-wide LDG.64 gathers).
// w[n,k,h] = r_k^(h+1), r_k = exp(-d^2/288). 12-op split per k:
//   heads 0-3 by chain (4 mul + 4 add, materializing c1..c4 = y*r..y*r^4),
//   heads 4-7 by acc = ffma2(c_h, dup(r^4), acc)  (r^(h+5) = r^(h+1)*r^4).
// Register economy for 24 warps/SM under the 85-reg cap: r^4 kept as 10
// scalars (dup built by 1 MOV/k), gather indices packed two-per-reg as 16-bit
// halves (idx*32 < 2^16). No smem, no barriers. prev carries the UNBLENDED
// agg[t-1]; streaming stores keep y L2-resident under the 197MB out-stream.
// ---------------------------------------------------------------------------
__global__ __launch_bounds__(128, 6) void k_gather(
    const float* __restrict__ dist,
    const float* __restrict__ bias,
    const int* __restrict__ nidx,          // int32 (JAX x64 disabled)
    float* __restrict__ out) {

    const int tid  = threadIdx.x;
    const int lane = tid & 31;             // f-pair
    const int wpid = tid >> 5;             // node within block (4 warps)
    const int bb   = blockIdx.y;
    const int n    = blockIdx.x * 4 + wpid;

    // Per-k ratio rd[k]=dup(r), r4 scalars, packed prescaled indices.
    unsigned long long rd[K_];
    float r4s[K_];
    #pragma unroll
    for (int k = 0; k < K_; ++k) {
        const float d = __ldg(&dist[n * K_ + k]);            // warp-broadcast
        const float r = __expf(-d * d * (1.0f / (H_ * 36.0f)));
        rd[k] = pk2(r, r);
        const float r2 = r * r;
        r4s[k] = r2 * r2;
    }
    unsigned int sxp[K_ / 2];              // (idx_{2j}*32)<<16 | (idx_{2j+1}*32)
    #pragma unroll
    for (int j = 0; j < K_ / 2; ++j) {
        const unsigned a = (unsigned)__ldg(&nidx[n * K_ + 2 * j])     * (F_ / 2);
        const unsigned b = (unsigned)__ldg(&nidx[n * K_ + 2 * j + 1]) * (F_ / 2);
        sxp[j] = (a << 16) | b;
    }

    const unsigned long long bdup =
        __ldg((const unsigned long long*)bias + lane);       // (b[2l], b[2l+1])

    const unsigned long long* yb =
        (const unsigned long long*)g_y + (size_t)(bb * T_) * N_ * (F_ / 2) + lane;
    float2* ob = (float2*)out + ((size_t)(bb * T_ * N_) + n) * (H_ * F_ / 2) + lane;

    unsigned long long prev[H_];
    unsigned long long acc[H_];
    const unsigned long long c0d = pk2(0.8f, 0.8f);
    const unsigned long long c1d = pk2(0.2f, 0.2f);

    #pragma unroll 1
    for (int t = 0; t < T_; ++t) {
        #pragma unroll
        for (int h = 0; h < H_; ++h) acc[h] = 0ull;

        #pragma unroll
        for (int j = 0; j < K_ / 2; ++j) {
            #pragma unroll
            for (int s = 0; s < 2; ++s) {
                const int k = 2 * j + s;
                const unsigned off = s ? (sxp[j] & 0xFFFFu) : (sxp[j] >> 16);
                const unsigned long long yv = __ldg(yb + off);   // dense LDG.64
                // chain: heads 0-3
                const unsigned long long c1 = mul2(yv, rd[k]);
                acc[0] = add2(acc[0], c1);
                const unsigned long long c2 = mul2(c1, rd[k]);
                acc[1] = add2(acc[1], c2);
                const unsigned long long c3 = mul2(c2, rd[k]);
                acc[2] = add2(acc[2], c3);
                const unsigned long long c4 = mul2(c3, rd[k]);
                acc[3] = add2(acc[3], c4);
                // r^4 jump: heads 4-7 (one FFMA each)
                const unsigned long long r4d = pk2(r4s[k], r4s[k]);
                acc[4] = ffma2(c1, r4d, acc[4]);
                acc[5] = ffma2(c2, r4d, acc[5]);
                acc[6] = ffma2(c3, r4d, acc[6]);
                acc[7] = ffma2(c4, r4d, acc[7]);
            }
        }

        if (t == 0) {
            #pragma unroll
            for (int h = 0; h < H_; ++h) {
                const float2 v = upk2(add2(acc[h], bdup));
                __stcs(&ob[h * (F_ / 2)],
                       make_float2(fmaxf(v.x, 0.f), fmaxf(v.y, 0.f)));
                prev[h] = acc[h];
            }
        } else {
            #pragma unroll
            for (int h = 0; h < H_; ++h) {
                const float2 v =
                    upk2(ffma2(acc[h], c0d, ffma2(prev[h], c1d, bdup)));
                __stcs(&ob[h * (F_ / 2)],
                       make_float2(fmaxf(v.x, 0.f), fmaxf(v.y, 0.f)));
                prev[h] = acc[h];                  // UNBLENDED carry
            }
        }

        yb += N_ * (F_ / 2);
        ob += (size_t)N_ * (H_ * F_ / 2);
    }
}

// ---------------------------------------------------------------------------
// Inputs: x f32[4,12,2000,64], neighbor_dist f32[2000,10], W f32[64,64],
// b f32[64], neighbor_idx i32[2000,10]. Output f32[4,12,2000,8,64].
// ---------------------------------------------------------------------------
extern "C" void kernel_launch(void* const* d_in, const int* in_sizes, int n_in,
                              void* d_out, int out_size) {
    const float* x    = (const float*)d_in[0];
    const float* dist = (const float*)d_in[1];
    const float* W    = (const float*)d_in[2];
    const float* bias = (const float*)d_in[3];
    const int*   nidx = (const int*)d_in[4];
    float*       out  = (float*)d_out;

    k_xw<<<(B_ * T_ * N_) / 128, 256>>>(x, W);

    dim3 g2(N_ / 4, B_);
    k_gather<<<g2, 128>>>(dist, bias, nidx, out);
}

// round 11
// speedup vs baseline: 1.7255x; 1.0414x over previous
#include <cuda_runtime.h>

#define B_ 4
#define T_ 12
#define N_ 2000
#define K_ 10
#define F_ 64
#define H_ 8

// Scratch: y = x @ W^T (24.6 MB). Static __device__ (no cudaMalloc allowed).
__device__ float g_y[B_ * T_ * N_ * F_];

// ---- packed-fp32 helpers (f32x2 ops only reachable via PTX) -----------------
__device__ __forceinline__ unsigned long long pk2(float a, float b) {
    unsigned long long r;
    asm("mov.b64 %0, {%1, %2};" : "=l"(r)
        : "r"(__float_as_uint(a)), "r"(__float_as_uint(b)));
    return r;
}
__device__ __forceinline__ unsigned long long ffma2(unsigned long long a,
                                                    unsigned long long b,
                                                    unsigned long long c) {
    unsigned long long d;
    asm("fma.rn.f32x2 %0, %1, %2, %3;" : "=l"(d) : "l"(a), "l"(b), "l"(c));
    return d;
}
__device__ __forceinline__ unsigned long long mul2(unsigned long long a,
                                                   unsigned long long b) {
    unsigned long long d;
    asm("mul.rn.f32x2 %0, %1, %2;" : "=l"(d) : "l"(a), "l"(b));
    return d;
}
__device__ __forceinline__ unsigned long long add2(unsigned long long a,
                                                   unsigned long long b) {
    unsigned long long d;
    asm("add.rn.f32x2 %0, %1, %2;" : "=l"(d) : "l"(a), "l"(b));
    return d;
}
__device__ __forceinline__ float2 upk2(unsigned long long a) {
    unsigned int lo, hi;
    asm("mov.b64 {%0, %1}, %2;" : "=r"(lo), "=r"(hi) : "l"(a));
    return make_float2(__uint_as_float(lo), __uint_as_float(hi));
}

// ---------------------------------------------------------------------------
// Kernel 1: y[row,f] = sum_fp x[row,fp] * W[f,fp].
// 750 blocks x 256 threads; 128-row tile; thread = 8 rows x 4 f (FFMA2 pairs).
// ---------------------------------------------------------------------------
__global__ __launch_bounds__(256) void k_xw(const float* __restrict__ x,
                                            const float* __restrict__ W) {
    __shared__ float xs[128][64];                  // 32 KB
    __shared__ unsigned long long Wp[64][32];      // 16 KB: Wp[fp][f2]=(W[2f2][fp],W[2f2+1][fp])

    const int tid = threadIdx.x;

    {
        const int f2 = tid >> 3, cg = tid & 7;
        const float* ra = W + (2 * f2) * 64 + cg * 8;
        const float* rb = W + (2 * f2 + 1) * 64 + cg * 8;
        const float4 a0 = *(const float4*)ra;
        const float4 a1 = *(const float4*)(ra + 4);
        const float4 b0 = *(const float4*)rb;
        const float4 b1 = *(const float4*)(rb + 4);
        Wp[cg * 8 + 0][f2] = pk2(a0.x, b0.x);
        Wp[cg * 8 + 1][f2] = pk2(a0.y, b0.y);
        Wp[cg * 8 + 2][f2] = pk2(a0.z, b0.z);
        Wp[cg * 8 + 3][f2] = pk2(a0.w, b0.w);
        Wp[cg * 8 + 4][f2] = pk2(a1.x, b1.x);
        Wp[cg * 8 + 5][f2] = pk2(a1.y, b1.y);
        Wp[cg * 8 + 6][f2] = pk2(a1.z, b1.z);
        Wp[cg * 8 + 7][f2] = pk2(a1.w, b1.w);
    }

    const size_t rbase = (size_t)blockIdx.x * 128;
    const float4* xg = (const float4*)(x + rbase * F_);
    #pragma unroll
    for (int j = tid; j < 128 * 16; j += 256) {              // coalesced
        ((float4*)xs)[j] = xg[j];
    }
    __syncthreads();

    const int fx = tid & 15;
    const int rg = tid >> 4;

    unsigned long long acc[8][2];
    #pragma unroll
    for (int r = 0; r < 8; ++r) { acc[r][0] = 0ull; acc[r][1] = 0ull; }

    #pragma unroll 4
    for (int fps = 0; fps < 16; ++fps) {
        const int fp = fps * 4;
        unsigned long long w0[4], w1[4];
        #pragma unroll
        for (int i = 0; i < 4; ++i) {
            const ulonglong2 wv = *(const ulonglong2*)&Wp[fp + i][fx * 2];
            w0[i] = wv.x; w1[i] = wv.y;
        }
        #pragma unroll
        for (int r = 0; r < 8; ++r) {
            const float4 xv = *(const float4*)&xs[rg * 8 + r][fp];   // broadcast
            unsigned long long xd;
            xd = pk2(xv.x, xv.x);
            acc[r][0] = ffma2(xd, w0[0], acc[r][0]); acc[r][1] = ffma2(xd, w1[0], acc[r][1]);
            xd = pk2(xv.y, xv.y);
            acc[r][0] = ffma2(xd, w0[1], acc[r][0]); acc[r][1] = ffma2(xd, w1[1], acc[r][1]);
            xd = pk2(xv.z, xv.z);
            acc[r][0] = ffma2(xd, w0[2], acc[r][0]); acc[r][1] = ffma2(xd, w1[2], acc[r][1]);
            xd = pk2(xv.w, xv.w);
            acc[r][0] = ffma2(xd, w0[3], acc[r][0]); acc[r][1] = ffma2(xd, w1[3], acc[r][1]);
        }
    }

    float* yp = g_y + rbase * F_;
    #pragma unroll
    for (int r = 0; r < 8; ++r) {
        const float2 lo = upk2(acc[r][0]);
        const float2 hi = upk2(acc[r][1]);
        *(float4*)&yp[(rg * 8 + r) * F_ + fx * 4] = make_float4(lo.x, lo.y, hi.x, hi.y);
    }
}

// ---------------------------------------------------------------------------
// Kernel 2: gather + heads + blend + relu, DOUBLE-BUFFERED over t.
// WARP = one node; LANE = one f-pair (dense warp-wide LDG.64 gathers).
// w[n,k,h] = r_k^(h+1): heads 0-3 via chain (c1..c4), heads 4-7 via one FFMA
// with dup(r^4). Indices are t-invariant, so t+1's 10 gathers are issued
// BEFORE t's math — t's ~350-cycle math window hides t+1's L2 latency (R10
// exposed ~400 cyc/t serially). r and r^4 kept as scalars; dup pairs rebuilt
// in-loop on the idle alu pipe to keep regs under the 128/4-CTA cap.
// prev carries UNBLENDED agg[t-1]; streaming stores keep y L2-resident.
// ---------------------------------------------------------------------------
struct B10 { unsigned long long v[K_]; };

__device__ __forceinline__ void load10(const unsigned long long* __restrict__ ybt,
                                       const int* sx, B10& b) {
    #pragma unroll
    for (int k = 0; k < K_; ++k) b.v[k] = __ldg(ybt + sx[k]);   // dense LDG.64
}

__device__ __forceinline__ void math_store(
    const B10& bf, const float* rs, const float* r4s,
    unsigned long long* prev,
    unsigned long long bdup, unsigned long long c0d, unsigned long long c1d,
    float2* __restrict__ ob, bool first) {

    unsigned long long acc[H_];
    #pragma unroll
    for (int h = 0; h < H_; ++h) acc[h] = 0ull;

    #pragma unroll
    for (int k = 0; k < K_; ++k) {
        const unsigned long long rd  = pk2(rs[k], rs[k]);     // alu-pipe MOVs
        const unsigned long long r4d = pk2(r4s[k], r4s[k]);
        const unsigned long long c1 = mul2(bf.v[k], rd);      // chain heads 0-3
        acc[0] = add2(acc[0], c1);
        const unsigned long long c2 = mul2(c1, rd);
        acc[1] = add2(acc[1], c2);
        const unsigned long long c3 = mul2(c2, rd);
        acc[2] = add2(acc[2], c3);
        const unsigned long long c4 = mul2(c3, rd);
        acc[3] = add2(acc[3], c4);
        acc[4] = ffma2(c1, r4d, acc[4]);                      // r^4 jump 4-7
        acc[5] = ffma2(c2, r4d, acc[5]);
        acc[6] = ffma2(c3, r4d, acc[6]);
        acc[7] = ffma2(c4, r4d, acc[7]);
    }

    if (first) {
        #pragma unroll
        for (int h = 0; h < H_; ++h) {
            const float2 v = upk2(add2(acc[h], bdup));
            __stcs(&ob[h * (F_ / 2)],
                   make_float2(fmaxf(v.x, 0.f), fmaxf(v.y, 0.f)));
            prev[h] = acc[h];
        }
    } else {
        #pragma unroll
        for (int h = 0; h < H_; ++h) {
            const float2 v = upk2(ffma2(acc[h], c0d, ffma2(prev[h], c1d, bdup)));
            __stcs(&ob[h * (F_ / 2)],
                   make_float2(fmaxf(v.x, 0.f), fmaxf(v.y, 0.f)));
            prev[h] = acc[h];                                 // UNBLENDED carry
        }
    }
}

__global__ __launch_bounds__(128, 4) void k_gather(
    const float* __restrict__ dist,
    const float* __restrict__ bias,
    const int* __restrict__ nidx,          // int32 (JAX x64 disabled)
    float* __restrict__ out) {

    const int tid  = threadIdx.x;
    const int lane = tid & 31;             // f-pair
    const int wpid = tid >> 5;             // node within block (4 warps)
    const int bb   = blockIdx.y;
    const int n    = blockIdx.x * 4 + wpid;

    float rs[K_], r4s[K_];
    int sx[K_];
    #pragma unroll
    for (int k = 0; k < K_; ++k) {
        const float d = __ldg(&dist[n * K_ + k]);            // warp-broadcast
        const float r = __expf(-d * d * (1.0f / (H_ * 36.0f)));
        rs[k] = r;
        const float r2 = r * r;
        r4s[k] = r2 * r2;
        sx[k] = __ldg(&nidx[n * K_ + k]) * (F_ / 2);
    }

    const unsigned long long bdup =
        __ldg((const unsigned long long*)bias + lane);       // (b[2l], b[2l+1])

    const int S = N_ * (F_ / 2);                             // t-stride (ull units)
    const unsigned long long* yb =
        (const unsigned long long*)g_y + (size_t)(bb * T_) * S + lane;
    float2* ob = (float2*)out + ((size_t)(bb * T_ * N_) + n) * (H_ * F_ / 2) + lane;
    const size_t OS = (size_t)N_ * (H_ * F_ / 2);            // out t-stride

    unsigned long long prev[H_];
    const unsigned long long c0d = pk2(0.8f, 0.8f);
    const unsigned long long c1d = pk2(0.2f, 0.2f);

    B10 A, Bb;
    load10(yb, sx, A);                                       // t=0 (only exposed latency)

    #pragma unroll 1
    for (int t = 0; t < T_; t += 2) {
        load10(yb + S, sx, Bb);                              // prefetch t+1
        math_store(A, rs, r4s, prev, bdup, c0d, c1d, ob, t == 0);
        if (t + 2 < T_) load10(yb + 2 * S, sx, A);           // prefetch t+2 (guarded: no OOB at tail)
        math_store(Bb, rs, r4s, prev, bdup, c0d, c1d, ob + OS, false);
        yb += 2 * S;
        ob += 2 * OS;
    }
}

// ---------------------------------------------------------------------------
// Inputs: x f32[4,12,2000,64], neighbor_dist f32[2000,10], W f32[64,64],
// b f32[64], neighbor_idx i32[2000,10]. Output f32[4,12,2000,8,64].
// ---------------------------------------------------------------------------
extern "C" void kernel_launch(void* const* d_in, const int* in_sizes, int n_in,
                              void* d_out, int out_size) {
    const float* x    = (const float*)d_in[0];
    const float* dist = (const float*)d_in[1];
    const float* W    = (const float*)d_in[2];
    const float* bias = (const float*)d_in[3];
    const int*   nidx = (const int*)d_in[4];
    float*       out  = (float*)d_out;

    k_xw<<<(B_ * T_ * N_) / 128, 256>>>(x, W);

    dim3 g2(N_ / 4, B_);
    k_gather<<<g2, 128>>>(dist, bias, nidx, out);
}